// round 3
// baseline (speedup 1.0000x reference)
#include <cuda_runtime.h>

// TSModel: 2-layer LSTM recurrence.
//   Layer 0: LSTMCell(1 -> 64). Layer 1: LSTMCell(64 -> 1), fed c0 (cell state!).
//   Output per step = c1 (layer-1 cell state). Gate order: i, f, g, o.
// B=2048 independent rows, T=1024 sequential steps.
//
// Design: persistent fp32 kernel. 128 CTAs x 128 threads. Each warp owns
// RPW=4 batch rows for the entire T loop (matvec + activations + layer 1),
// so there are NO block-level syncs inside the time loop. W_hh0 lives
// transposed in SMEM (64 KB, shared by the CTA's 4 warps); h0 state lives in
// per-warp SMEM rows; c0/h1/c1 live in registers distributed across lanes
// (lane j owns units 2j, 2j+1).

#define UNITS 64
#define TSTEPS 1024
#define BATCH 2048
#define RPW 4                      // rows per warp
#define WARPS_PER_CTA 4
#define ROWS_PER_CTA (RPW * WARPS_PER_CTA)   // 16
#define NCTA (BATCH / ROWS_PER_CTA)          // 128
#define SMEM_BYTES ((256 * UNITS + ROWS_PER_CTA * UNITS) * (int)sizeof(float))

__device__ __forceinline__ float sigf(float x) {
    // 1/(1+e^-x); safe at both tails (exp->inf => 0, exp->0 => 1)
    return __fdividef(1.0f, 1.0f + __expf(-x));
}
__device__ __forceinline__ float tanhfast(float x) {
    // 2*sigmoid(2x)-1; safe at both tails
    return 2.0f * __fdividef(1.0f, 1.0f + __expf(-2.0f * x)) - 1.0f;
}

__global__ void __launch_bounds__(WARPS_PER_CTA * 32)
lstm_kernel(const float* __restrict__ input,
            const float* __restrict__ W_ih0, const float* __restrict__ W_hh0,
            const float* __restrict__ b_ih0, const float* __restrict__ b_hh0,
            const float* __restrict__ W_ih1, const float* __restrict__ W_hh1,
            const float* __restrict__ b_ih1, const float* __restrict__ b_hh1,
            float* __restrict__ out)
{
    extern __shared__ float smem[];
    float* Wt  = smem;                 // [64][256]  Wt[k*256 + g] = W_hh0[g][k]
    float* h0s = smem + 256 * UNITS;   // [16][64]   per-CTA h0 state

    const int tid  = threadIdx.x;
    const int wid  = tid >> 5;
    const int lane = tid & 31;

    // One-time: transpose W_hh0 (256x64) into SMEM, zero h0 state.
    for (int i = tid; i < 256 * UNITS; i += blockDim.x) {
        int g = i >> 6, k = i & 63;
        Wt[k * 256 + g] = W_hh0[i];
    }
    for (int i = tid; i < ROWS_PER_CTA * UNITS; i += blockDim.x) h0s[i] = 0.0f;
    __syncthreads();

    // Per-lane constants. Lane j owns gate columns {2j, 2j+1} in each of the
    // 4 gate groups (i,f,g,o), i.e. hidden units u0=2j, u1=2j+1.
    float2 bias[4], wih[4], w1[4];
    float  wh1r[4], b1r[4];
#pragma unroll
    for (int q = 0; q < 4; q++) {
        int g = 64 * q + 2 * lane;
        bias[q] = make_float2(b_ih0[g] + b_hh0[g], b_ih0[g + 1] + b_hh0[g + 1]);
        wih[q]  = make_float2(W_ih0[g], W_ih0[g + 1]);
        w1[q]   = make_float2(W_ih1[q * UNITS + 2 * lane],
                              W_ih1[q * UNITS + 2 * lane + 1]);
        wh1r[q] = W_hh1[q];
        b1r[q]  = b_ih1[q] + b_hh1[q];
    }

    const int row0 = blockIdx.x * ROWS_PER_CTA + wid * RPW;  // this warp's rows
    float* h0w = h0s + (wid * RPW) * UNITS;
    const float2* Wt2 = (const float2*)Wt;

    float c0[RPW][2] = {};       // layer-0 cell state for units u0,u1
    float h1[RPW] = {}, c1[RPW] = {};   // layer-1 state (replicated per lane)

    // x staging: xcur[r] holds input[row0+r][t_blk + lane]; double buffered.
    float xcur[RPW], xnxt[RPW];
#pragma unroll
    for (int r = 0; r < RPW; r++) xcur[r] = input[(row0 + r) * TSTEPS + lane];

    for (int t = 0; t < TSTEPS; t++) {
        const int tm = t & 31;
        if (tm == 0) {
            const int tn = t + 32;
#pragma unroll
            for (int r = 0; r < RPW; r++)
                xnxt[r] = (tn < TSTEPS) ? input[(row0 + r) * TSTEPS + tn + lane] : 0.0f;
        }

        // ---- init gate accumulators: bias + x_t * W_ih0 ----
        float2 acc[RPW][4];
#pragma unroll
        for (int r = 0; r < RPW; r++) {
            float xv = __shfl_sync(0xffffffffu, xcur[r], tm);
#pragma unroll
            for (int q = 0; q < 4; q++) {
                acc[r][q].x = fmaf(xv, wih[q].x, bias[q].x);
                acc[r][q].y = fmaf(xv, wih[q].y, bias[q].y);
            }
        }
        __syncwarp();   // h0 writes from step t-1 visible to all lanes

        // ---- matvec: acc[r][q] += sum_k h0[r][k] * Wt[k][64q + 2*lane (+1)] ----
#pragma unroll 8
        for (int k2 = 0; k2 < 32; k2++) {
            float2 wA[4], wB[4];
#pragma unroll
            for (int q = 0; q < 4; q++) {
                wA[q] = Wt2[(2 * k2)     * 128 + 32 * q + lane];
                wB[q] = Wt2[(2 * k2 + 1) * 128 + 32 * q + lane];
            }
#pragma unroll
            for (int r = 0; r < RPW; r++) {
                float2 hv = *(const float2*)&h0w[r * UNITS + 2 * k2];
#pragma unroll
                for (int q = 0; q < 4; q++) {
                    acc[r][q].x = fmaf(hv.x, wA[q].x, acc[r][q].x);
                    acc[r][q].y = fmaf(hv.x, wA[q].y, acc[r][q].y);
                    acc[r][q].x = fmaf(hv.y, wB[q].x, acc[r][q].x);
                    acc[r][q].y = fmaf(hv.y, wB[q].y, acc[r][q].y);
                }
            }
        }
        __syncwarp();   // all matvec reads of h0 done before rewriting it

        // ---- layer-0 elementwise + layer-1 partial dot products ----
        float p[RPW][4];
#pragma unroll
        for (int r = 0; r < RPW; r++) {
            float ix = sigf(acc[r][0].x),     iy = sigf(acc[r][0].y);
            float fx = sigf(acc[r][1].x),     fy = sigf(acc[r][1].y);
            float gx = tanhfast(acc[r][2].x), gy = tanhfast(acc[r][2].y);
            float ox = sigf(acc[r][3].x),     oy = sigf(acc[r][3].y);
            float cnx = fmaf(fx, c0[r][0], ix * gx);
            float cny = fmaf(fy, c0[r][1], iy * gy);
            c0[r][0] = cnx; c0[r][1] = cny;
            float hnx = ox * tanhfast(cnx);
            float hny = oy * tanhfast(cny);
            *(float2*)&h0w[r * UNITS + 2 * lane] = make_float2(hnx, hny);
            // layer 1 input is the CELL state c0_new (quirk of the reference)
#pragma unroll
            for (int q = 0; q < 4; q++)
                p[r][q] = fmaf(cnx, w1[q].x, cny * w1[q].y);
        }

        // ---- butterfly-reduce the 16 layer-1 gate sums across lanes ----
#pragma unroll
        for (int s = 16; s > 0; s >>= 1) {
#pragma unroll
            for (int r = 0; r < RPW; r++)
#pragma unroll
                for (int q = 0; q < 4; q++)
                    p[r][q] += __shfl_xor_sync(0xffffffffu, p[r][q], s);
        }

        // ---- layer-1 elementwise (replicated on all lanes) ----
#pragma unroll
        for (int r = 0; r < RPW; r++) {
            float i1 = sigf(fmaf(wh1r[0], h1[r], p[r][0] + b1r[0]));
            float f1 = sigf(fmaf(wh1r[1], h1[r], p[r][1] + b1r[1]));
            float g1 = tanhfast(fmaf(wh1r[2], h1[r], p[r][2] + b1r[2]));
            float o1 = sigf(fmaf(wh1r[3], h1[r], p[r][3] + b1r[3]));
            float c1n = fmaf(f1, c1[r], i1 * g1);
            c1[r] = c1n;
            h1[r] = o1 * tanhfast(c1n);
        }

        // output: out[b][t] = c1n. Lanes 0..3 each write their row (static select
        // to avoid dynamic register indexing).
        {
            float ov = c1[0];
            if (lane == 1) ov = c1[1];
            if (lane == 2) ov = c1[2];
            if (lane == 3) ov = c1[3];
            if (lane < RPW) out[(row0 + lane) * TSTEPS + t] = ov;
        }

        if (tm == 31) {
#pragma unroll
            for (int r = 0; r < RPW; r++) xcur[r] = xnxt[r];
        }
    }
}

extern "C" void kernel_launch(void* const* d_in, const int* in_sizes, int n_in,
                              void* d_out, int out_size) {
    const float* input = (const float*)d_in[0];
    const float* W_ih0 = (const float*)d_in[1];
    const float* W_hh0 = (const float*)d_in[2];
    const float* b_ih0 = (const float*)d_in[3];
    const float* b_hh0 = (const float*)d_in[4];
    const float* W_ih1 = (const float*)d_in[5];
    const float* W_hh1 = (const float*)d_in[6];
    const float* b_ih1 = (const float*)d_in[7];
    const float* b_hh1 = (const float*)d_in[8];
    float* out = (float*)d_out;

    cudaFuncSetAttribute(lstm_kernel,
                         cudaFuncAttributeMaxDynamicSharedMemorySize, SMEM_BYTES);
    lstm_kernel<<<NCTA, WARPS_PER_CTA * 32, SMEM_BYTES>>>(
        input, W_ih0, W_hh0, b_ih0, b_hh0, W_ih1, W_hh1, b_ih1, b_hh1, out);
}